// round 16
// baseline (speedup 1.0000x reference)
#include <cuda_runtime.h>
#include <cstddef>

// GraphSage gather + cosine top-16 + mean.  (Round 16 = R12 body, 2-launch phase split)
//   d_in[0] nodes  : int32 [N]
//   d_in[1] neigh  : int32 [N, 32]
//   d_in[2] u2e_visual : f32 [500000, 64]
//   d_in[3] u2e_text   : f32 [500000, 64]
// Output: f32 concat(u_v, u_t, v_agg, t_agg), each [N, 64].
//
// Verified-108.9us R12 body; the only change is the prologue: modality is
// now selected by kernel ARGUMENTS (emb / ctr_out / agg_out) and the host
// issues two sequential launches (visual, then text). Same-stream kernels
// are hardware-serialized, so each phase's random-gather working set is
// EXACTLY one ~128MB table (~L2 size) — no transition-window mixing.
// Hard-won structure rules (do not perturb):
//  * __launch_bounds__(256, 7) is load-bearing (occ-8 collapsed to ~146us).
//  * The sim loop's IN-LOOP predicated keep of (dot, nsq) pins ptxas's load
//    schedule in the "good" mode; front-batched / xor-rank / cache-policy
//    variants all flipped to a ~145us bad schedule.
//  * Single hoisted fdividef after a 2-shfl redistribute (R12 win).
//  * __fns-compacted unconditional mean loop (R11 win).
//  * Ranking by dot*|dot|/||v||^2: strictly monotone in cosine; center norm
//    is a positive per-node constant -> identical top-16 set to reference.

#define DEG   32
#define TOPK  16
#define EMB   64

__global__ __launch_bounds__(256, 7) void gs_kernel(
    const int*   __restrict__ nodes,
    const int*   __restrict__ neigh,
    const float* __restrict__ emb,
    float*       __restrict__ ctr_out,
    float*       __restrict__ agg_out,
    int n)
{
    const unsigned FULL = 0xffffffffu;
    int wg = (int)((blockIdx.x * blockDim.x + threadIdx.x) >> 5);
    if (wg >= n) return;
    int lane = threadIdx.x & 31;
    int node = wg;

    int g = lane >> 3;     // 8-lane group id (0..3) — one neighbor per group
    int s = lane & 7;      // sub-lane within group — 8 floats per lane

    // ---- center gather (lane s holds float4 s and s+8 of the row) ----
    int cidx = __ldcs(nodes + node);
    const float4* crow = (const float4*)(emb + (size_t)cidx * EMB);
    float4 ua = __ldg(crow + s);
    float4 ub = __ldg(crow + s + 8);

    float4* cout = (float4*)(ctr_out + (size_t)node * EMB);
    if (g == 0) { __stcs(cout + s, ua); __stcs(cout + s + 8, ub); }

    // ---- neighbor indices: lane k holds neigh[node][k] ----
    int nidx = __ldcs(neigh + (size_t)node * DEG + lane);

    // ---- per-neighbor (dot, nsq); in-loop predicated keep (schedule pin) ----
    float fd = 0.0f, fn = 1.0f;
    #pragma unroll
    for (int it = 0; it < 8; it++) {
        int j = __shfl_sync(FULL, nidx, 4 * it + g);
        const float4* vrow = (const float4*)(emb + (size_t)j * EMB);
        float4 va = __ldg(vrow + s);
        float4 vb = __ldg(vrow + s + 8);
        float dot = va.x * ua.x + va.y * ua.y + va.z * ua.z + va.w * ua.w
                  + vb.x * ub.x + vb.y * ub.y + vb.z * ub.z + vb.w * ub.w;
        float nsq = va.x * va.x + va.y * va.y + va.z * va.z + va.w * va.w
                  + vb.x * vb.x + vb.y * vb.y + vb.z * vb.z + vb.w * vb.w;
        #pragma unroll
        for (int d = 1; d < 8; d <<= 1) {        // 3-step butterfly per group
            dot += __shfl_xor_sync(FULL, dot, d);
            nsq += __shfl_xor_sync(FULL, nsq, d);
        }
        if (s == it) { fd = dot; fn = nsq; }     // lane L keeps nbr 4*(L&7)+(L>>3)
    }
    // redistribute so lane j holds neighbor j's pair: src(j) = ((j&3)<<3)|(j>>2)
    int src = ((lane & 3) << 3) | (lane >> 2);
    float rd = __shfl_sync(FULL, fd, src);
    float rn = __shfl_sync(FULL, fn, src);
    // ranking value: dot*|dot|/||v||^2 — strictly monotone in cosine
    // (center norm is a positive per-node constant, irrelevant to order).
    float mysim = __fdividef(rd * fabsf(rd), rn + 1e-20f);

    // ---- stable top-16 via rank count (matches jax.lax.top_k tie-break) ----
    int cnt = 0;
    #pragma unroll
    for (int jl = 0; jl < DEG; jl++) {
        float o = __shfl_sync(FULL, mysim, jl);
        cnt += (o > mysim) || (o == mysim && jl < lane);
    }
    unsigned sel = __ballot_sync(FULL, cnt < TOPK);   // exactly TOPK bits set

    // ---- compact the 16 selected indices into lanes 0..15 ----
    int pos  = __fns(sel, 0, 1 + lane);               // lane>=16: unused
    int jsel = __shfl_sync(FULL, nidx, pos & 31);

    // ---- mean: 8 unconditional iterations, 2 selected rows each ----
    int half = lane >> 4;   // which of the pair this half-warp handles
    int sub  = lane & 15;   // float4 slot within the 64-float row
    float4 acc = make_float4(0.f, 0.f, 0.f, 0.f);
    #pragma unroll
    for (int i = 0; i < 8; i++) {
        int j = __shfl_sync(FULL, jsel, 2 * i + half);
        float4 v = __ldg((const float4*)(emb + (size_t)j * EMB) + sub);
        acc.x += v.x; acc.y += v.y; acc.z += v.z; acc.w += v.w;
    }
    acc.x += __shfl_xor_sync(FULL, acc.x, 16);
    acc.y += __shfl_xor_sync(FULL, acc.y, 16);
    acc.z += __shfl_xor_sync(FULL, acc.z, 16);
    acc.w += __shfl_xor_sync(FULL, acc.w, 16);

    if (half == 0) {
        const float sc = 1.0f / (float)TOPK;
        float4 r = make_float4(acc.x * sc, acc.y * sc, acc.z * sc, acc.w * sc);
        float4* aout = (float4*)(agg_out + (size_t)node * EMB);
        __stcs(aout + sub, r);
    }
}

extern "C" void kernel_launch(void* const* d_in, const int* in_sizes, int n_in,
                              void* d_out, int out_size) {
    const int*   nodes = (const int*)d_in[0];
    const int*   neigh = (const int*)d_in[1];
    const float* uv    = (const float*)d_in[2];
    const float* ut    = (const float*)d_in[3];
    float*       out   = (float*)d_out;
    int n = in_sizes[0];
    size_t nn = (size_t)n * EMB;
    int threads = 256;
    int blocks = (n * 32 + threads - 1) / threads;
    // Phase 1: visual table only (u_v -> out[0], v_agg -> out[2nn])
    gs_kernel<<<blocks, threads>>>(nodes, neigh, uv, out, out + 2 * nn, n);
    // Phase 2: text table only (u_t -> out[nn], t_agg -> out[3nn])
    gs_kernel<<<blocks, threads>>>(nodes, neigh, ut, out + nn, out + 3 * nn, n);
}

// round 17
// speedup vs baseline: 1.1632x; 1.1632x over previous
#include <cuda_runtime.h>
#include <cstddef>

// GraphSage gather + cosine top-16 + mean.  (FINAL = byte-exact R12, 108.9us)
//   d_in[0] nodes  : int32 [N]
//   d_in[1] neigh  : int32 [N, 32]
//   d_in[2] u2e_visual : f32 [500000, 64]
//   d_in[3] u2e_text   : f32 [500000, 64]
// Output: f32 concat(u_v, u_t, v_agg, t_agg), each [N, 64].
//
// Verified twice at 108.9/109.0us. Session findings (do not perturb):
//  * One warp per (node, modality); modality-major task order keeps each
//    phase's random-gather working set to a single ~128MB table (~L2 size).
//    A 2-launch hard split was WORSE (per-launch schedule degraded).
//  * __launch_bounds__(256, 7) is load-bearing (occ-8 collapsed to ~146us).
//  * The sim loop's IN-LOOP predicated keep of (dot, nsq) pins ptxas's load
//    schedule in the "good" mode (~655 instr, interleaved loads). Seven
//    textual perturbations (front-batching x2, exchange tree, bitonic sort,
//    cache policies x2, xor-rank, occ-8, 2-launch) ALL flipped compilation
//    into a ~145us bad schedule via cross-CTA L1tex queue contention.
//  * Single hoisted fdividef after a 2-shfl redistribute (R12 win, -8.4us).
//  * __fns-compacted unconditional mean loop (R11 win, -3.7us).
//  * Ranking by dot*|dot|/||v||^2: strictly monotone in cosine; center norm
//    is a positive per-node constant -> identical top-16 set + tie-break to
//    jax.lax.top_k. Selected rows averaged UN-normalized, as the reference.

#define DEG   32
#define TOPK  16
#define EMB   64

__global__ __launch_bounds__(256, 7) void gs_kernel(
    const int*   __restrict__ nodes,
    const int*   __restrict__ neigh,
    const float* __restrict__ uv,
    const float* __restrict__ ut,
    float*       __restrict__ out,
    int n)
{
    const unsigned FULL = 0xffffffffu;
    int wg = (int)((blockIdx.x * blockDim.x + threadIdx.x) >> 5);
    if (wg >= 2 * n) return;
    int lane = threadIdx.x & 31;

    // modality-major task order: [0,n) = visual, [n,2n) = text
    int m    = (wg >= n) ? 1 : 0;
    int node = wg - m * n;
    const float* __restrict__ emb = m ? ut : uv;

    int g = lane >> 3;     // 8-lane group id (0..3) — one neighbor per group
    int s = lane & 7;      // sub-lane within group — 8 floats per lane

    // ---- center gather (lane s holds float4 s and s+8 of the row) ----
    int cidx = __ldcs(nodes + node);
    const float4* crow = (const float4*)(emb + (size_t)cidx * EMB);
    float4 ua = __ldg(crow + s);
    float4 ub = __ldg(crow + s + 8);

    size_t nn = (size_t)n * EMB;
    float4* cout = (float4*)(out + (size_t)m * nn + (size_t)node * EMB);
    if (g == 0) { __stcs(cout + s, ua); __stcs(cout + s + 8, ub); }

    // ---- neighbor indices: lane k holds neigh[node][k] ----
    int nidx = __ldcs(neigh + (size_t)node * DEG + lane);

    // ---- per-neighbor (dot, nsq); in-loop predicated keep (schedule pin) ----
    float fd = 0.0f, fn = 1.0f;
    #pragma unroll
    for (int it = 0; it < 8; it++) {
        int j = __shfl_sync(FULL, nidx, 4 * it + g);
        const float4* vrow = (const float4*)(emb + (size_t)j * EMB);
        float4 va = __ldg(vrow + s);
        float4 vb = __ldg(vrow + s + 8);
        float dot = va.x * ua.x + va.y * ua.y + va.z * ua.z + va.w * ua.w
                  + vb.x * ub.x + vb.y * ub.y + vb.z * ub.z + vb.w * ub.w;
        float nsq = va.x * va.x + va.y * va.y + va.z * va.z + va.w * va.w
                  + vb.x * vb.x + vb.y * vb.y + vb.z * vb.z + vb.w * vb.w;
        #pragma unroll
        for (int d = 1; d < 8; d <<= 1) {        // 3-step butterfly per group
            dot += __shfl_xor_sync(FULL, dot, d);
            nsq += __shfl_xor_sync(FULL, nsq, d);
        }
        if (s == it) { fd = dot; fn = nsq; }     // lane L keeps nbr 4*(L&7)+(L>>3)
    }
    // redistribute so lane j holds neighbor j's pair: src(j) = ((j&3)<<3)|(j>>2)
    int src = ((lane & 3) << 3) | (lane >> 2);
    float rd = __shfl_sync(FULL, fd, src);
    float rn = __shfl_sync(FULL, fn, src);
    // ranking value: dot*|dot|/||v||^2 — strictly monotone in cosine
    // (center norm is a positive per-node constant, irrelevant to order).
    float mysim = __fdividef(rd * fabsf(rd), rn + 1e-20f);

    // ---- stable top-16 via rank count (matches jax.lax.top_k tie-break) ----
    int cnt = 0;
    #pragma unroll
    for (int jl = 0; jl < DEG; jl++) {
        float o = __shfl_sync(FULL, mysim, jl);
        cnt += (o > mysim) || (o == mysim && jl < lane);
    }
    unsigned sel = __ballot_sync(FULL, cnt < TOPK);   // exactly TOPK bits set

    // ---- compact the 16 selected indices into lanes 0..15 ----
    int pos  = __fns(sel, 0, 1 + lane);               // lane>=16: unused
    int jsel = __shfl_sync(FULL, nidx, pos & 31);

    // ---- mean: 8 unconditional iterations, 2 selected rows each ----
    int half = lane >> 4;   // which of the pair this half-warp handles
    int sub  = lane & 15;   // float4 slot within the 64-float row
    float4 acc = make_float4(0.f, 0.f, 0.f, 0.f);
    #pragma unroll
    for (int i = 0; i < 8; i++) {
        int j = __shfl_sync(FULL, jsel, 2 * i + half);
        float4 v = __ldg((const float4*)(emb + (size_t)j * EMB) + sub);
        acc.x += v.x; acc.y += v.y; acc.z += v.z; acc.w += v.w;
    }
    acc.x += __shfl_xor_sync(FULL, acc.x, 16);
    acc.y += __shfl_xor_sync(FULL, acc.y, 16);
    acc.z += __shfl_xor_sync(FULL, acc.z, 16);
    acc.w += __shfl_xor_sync(FULL, acc.w, 16);

    if (half == 0) {
        const float sc = 1.0f / (float)TOPK;
        float4 r = make_float4(acc.x * sc, acc.y * sc, acc.z * sc, acc.w * sc);
        float4* aout = (float4*)(out + (size_t)(2 + m) * nn + (size_t)node * EMB);
        __stcs(aout + sub, r);
    }
}

extern "C" void kernel_launch(void* const* d_in, const int* in_sizes, int n_in,
                              void* d_out, int out_size) {
    const int*   nodes = (const int*)d_in[0];
    const int*   neigh = (const int*)d_in[1];
    const float* uv    = (const float*)d_in[2];
    const float* ut    = (const float*)d_in[3];
    float*       out   = (float*)d_out;
    int n = in_sizes[0];
    int warps = 2 * n;
    int threads = 256;
    int blocks = (warps * 32 + threads - 1) / threads;
    gs_kernel<<<blocks, threads>>>(nodes, neigh, uv, ut, out, n);
}